// round 13
// baseline (speedup 1.0000x reference)
#include <cuda_runtime.h>
#include <cuda_fp16.h>
#include <cstdint>

#define NPTS   200000
#define CIN    64
#define COUT   16
#define SXD    998
#define SYD    998
#define SZD    38
#define YZ     37924          /* SYD*SZD */
#define SENTV  37848152u
#define NKTOT  5400000        /* NPTS*27 */
#define WORDS  1182755
#define CHUNK  4096
#define NPART  289
#define WPAD   (NPART*CHUNK)
#define ZBLK   (WPAD/1024)
#define FOB    512

#define NOUT   432            /* 27*16 */
#define BSTR   72             /* padded row stride (fp16 elems) = 144B */
#define TILEM  128
#define NT     1563           /* ceil(200000/128) */
#define KB0    14             /* k split: [0,14) and [14,27) */
#define NSTREAM 222           /* tile streams; grid = 2*NSTREAM = 444 = 3/SM */

/* smem layout (bytes) */
#define AH_OFF   0            /* 128*144 = 18432 */
#define AL_OFF   18432
#define BH_OFF   36864        /* 224*144 = 32256 max */
#define SMEM_SZ  69120        /* 3 CTAs/SM */

// ---------------- device scratch ----------------
__device__ __align__(16) unsigned g_bitmap[WPAD];
__device__ __align__(16) unsigned g_coll[WPAD];
__device__ __align__(16) unsigned g_pref[WPAD];
__device__ __align__(16) unsigned g_rank[27 * NPTS];
__device__ __align__(16) unsigned short g_Bh[NOUT * BSTR];
__device__ unsigned g_part[NPART];
__device__ unsigned g_M;

static __device__ __forceinline__ uint32_t smem_u32(const void* p) {
    uint32_t a;
    asm("{ .reg .u64 t; cvta.to.shared.u64 t, %1; cvt.u32.u64 %0, t; }" : "=r"(a) : "l"(p));
    return a;
}

#define MMA(C, A, b0v, b1v) \
    asm volatile("mma.sync.aligned.m16n8k16.row.col.f32.f16.f16.f32 " \
        "{%0,%1,%2,%3},{%4,%5,%6,%7},{%8,%9},{%0,%1,%2,%3};" \
        : "+f"((C)[0]), "+f"((C)[1]), "+f"((C)[2]), "+f"((C)[3]) \
        : "r"((A)[0]), "r"((A)[1]), "r"((A)[2]), "r"((A)[3]), "r"(b0v), "r"(b1v))

// ---------------- kernels ----------------
// zero both bitmaps + build padded fp16 B [og][c]
__global__ void k_zero(const float* __restrict__ W) {
    if (blockIdx.x < 2 * ZBLK) {
        unsigned* dst = (blockIdx.x < ZBLK) ? g_bitmap : g_coll;
        unsigned b = (blockIdx.x < ZBLK) ? blockIdx.x : blockIdx.x - ZBLK;
        unsigned i = b * 1024 + threadIdx.x * 4;
        *reinterpret_cast<uint4*>(&dst[i]) = make_uint4(0u, 0u, 0u, 0u);
    } else {
        int k = blockIdx.x - 2 * ZBLK;
#pragma unroll
        for (int u = 0; u < 4; u++) {
            int idx = threadIdx.x + u * 256;
            int o = idx >> 6, c = idx & 63;
            float v = W[k * 1024 + c * 16 + o];
            __half h = __float2half_rn(v);
            int og = k * 16 + o;
            g_Bh[og * BSTR + c] = reinterpret_cast<unsigned short&>(h);
        }
    }
}

__global__ void k_mark(const int4* __restrict__ coords) {
    int n = blockIdx.x * blockDim.x + threadIdx.x;
    if (n >= NPTS) return;
    int4 c = coords[n];
#pragma unroll
    for (int k = 0; k < 27; k++) {
        int ox = c.y - k / 9;
        int oy = c.z - (k / 3) % 3;
        int oz = c.w - k % 3;
        if ((unsigned)ox < SXD && (unsigned)oy < SYD && (unsigned)oz < SZD) {
            unsigned lin = (unsigned)ox * YZ + (unsigned)oy * SZD + (unsigned)oz;
            unsigned bit = 1u << (lin & 31);
            unsigned old = atomicOr(&g_bitmap[lin >> 5], bit);
            if (old & bit) atomicOr(&g_coll[lin >> 5], bit);
        }
    }
}

__global__ void k_scan1() {
    __shared__ unsigned sh[256];
    unsigned base = blockIdx.x * CHUNK + threadIdx.x * 16;
    unsigned s = 0;
#pragma unroll
    for (int i = 0; i < 16; i += 4) {
        uint4 v = *reinterpret_cast<const uint4*>(&g_bitmap[base + i]);
        s += __popc(v.x) + __popc(v.y) + __popc(v.z) + __popc(v.w);
    }
    sh[threadIdx.x] = s;
    __syncthreads();
    for (int off = 128; off > 0; off >>= 1) {
        if (threadIdx.x < (unsigned)off) sh[threadIdx.x] += sh[threadIdx.x + off];
        __syncthreads();
    }
    if (threadIdx.x == 0) g_part[blockIdx.x] = sh[0];
}

__global__ void k_scan2() {
    __shared__ unsigned sh[512];
    unsigned t = threadIdx.x;
    unsigned v = (t < NPART) ? g_part[t] : 0u;
    sh[t] = v;
    __syncthreads();
    for (int off = 1; off < 512; off <<= 1) {
        unsigned add = (t >= (unsigned)off) ? sh[t - off] : 0u;
        __syncthreads();
        sh[t] += add;
        __syncthreads();
    }
    if (t < NPART) g_part[t] = sh[t] - v;
    if (t == NPART - 1) g_M = sh[t];
}

// combo: blocks [0,NPART): per-word prefix + bias-init of COLLISION rows only;
//        remaining blocks: zero tail rows (j>=M) + SENT-pad uniq tail
__global__ void k_combo(float4* __restrict__ out4, const float4* __restrict__ bias4,
                        float* __restrict__ uniqf) {
    if (blockIdx.x < NPART) {
        float4 bsv[4];
#pragma unroll
        for (int j = 0; j < 4; j++) bsv[j] = __ldg(&bias4[j]);
        __shared__ unsigned sh[256];
        unsigned base = blockIdx.x * CHUNK + threadIdx.x * 16;
        unsigned w[16];
#pragma unroll
        for (int i = 0; i < 16; i += 4)
            *reinterpret_cast<uint4*>(&w[i]) = *reinterpret_cast<const uint4*>(&g_bitmap[base + i]);
        unsigned s = 0;
#pragma unroll
        for (int i = 0; i < 16; i++) s += __popc(w[i]);
        sh[threadIdx.x] = s;
        __syncthreads();
        for (int off = 1; off < 256; off <<= 1) {
            unsigned add = (threadIdx.x >= (unsigned)off) ? sh[threadIdx.x - off] : 0u;
            __syncthreads();
            sh[threadIdx.x] += add;
            __syncthreads();
        }
        unsigned run = g_part[blockIdx.x] + (sh[threadIdx.x] - s);
#pragma unroll 1
        for (int i = 0; i < 16; i++) {
            g_pref[base + i] = run;
            unsigned bits = w[i];
            if (bits) {
                unsigned collw = g_coll[base + i] & bits;
                unsigned r0 = run;
                run += __popc(bits);
                while (collw) {
                    unsigned b = __ffs(collw) - 1u;
                    collw &= collw - 1u;
                    unsigned r = r0 + __popc(bits & ((1u << b) - 1u));
                    float4* o = out4 + (size_t)r * 4;
                    o[0] = bsv[0]; o[1] = bsv[1]; o[2] = bsv[2]; o[3] = bsv[3];
                }
            }
        }
    } else {
        unsigned gt = (blockIdx.x - NPART) * 256u + threadIdx.x;
        unsigned stride = (gridDim.x - NPART) * 256u;
        unsigned M = g_M;
        const float4 z4 = make_float4(0.f, 0.f, 0.f, 0.f);
        for (unsigned i = M * 4u + gt; i < (unsigned)NKTOT * 4u; i += stride)
            out4[i] = z4;
        for (unsigned j = M + gt; j < (unsigned)NKTOT; j += stride)
            uniqf[j] = 37848152.0f;
    }
}

// precompute rank[k][n] (0xFFFFFFFF = invalid; bit31 = collision)
__global__ void k_rank(const int4* __restrict__ coords) {
    int n = blockIdx.x * blockDim.x + threadIdx.x;
    if (n >= NPTS) return;
    int4 c = coords[n];
#pragma unroll
    for (int k = 0; k < 27; k++) {
        int ox = c.y - k / 9;
        int oy = c.z - (k / 3) % 3;
        int oz = c.w - k % 3;
        unsigned rank = 0xFFFFFFFFu;
        if ((unsigned)ox < SXD && (unsigned)oy < SYD && (unsigned)oz < SZD) {
            unsigned lin = (unsigned)ox * YZ + (unsigned)oy * SZD + (unsigned)oz;
            unsigned word = lin >> 5;
            unsigned bpos = lin & 31;
            rank = __ldg(&g_pref[word]) +
                   __popc(__ldg(&g_bitmap[word]) & ((1u << bpos) - 1u));
            if ((__ldg(&g_coll[word]) >> bpos) & 1u) rank |= 0x80000000u;
        }
        g_rank[k * NPTS + n] = rank;
    }
}

__global__ void k_emit(float* __restrict__ uniqf) {
    unsigned i = blockIdx.x * blockDim.x + threadIdx.x;
    if (i >= WORDS) return;
    unsigned bits = g_bitmap[i];
    if (!bits) return;
    unsigned r = g_pref[i];
    unsigned vbase = i << 5;
    while (bits) {
        unsigned b = __ffs(bits) - 1u;
        bits &= bits - 1u;
        uniqf[r++] = (float)(vbase + b);
    }
}

// ---- persistent fp16-split HMMA GEMM + register-direct collision-split scatter ----
__global__ void __launch_bounds__(256, 3) k_gemm(
    const float4* __restrict__ feats4, float* __restrict__ out,
    const float2* __restrict__ bias2)
{
    extern __shared__ char smem[];
    uint32_t sb = smem_u32(smem);
    int tid = threadIdx.x;
    int wid = tid >> 5;
    int lane = tid & 31;
    int khalf = blockIdx.x & 1;
    int stream = blockIdx.x >> 1;
    int kbeg = khalf ? KB0 : 0;
    int kend = khalf ? 27 : KB0;

    // stage B (fp16) for our k-range ONCE
    {
        int nu4 = (kend - kbeg) * 144;
        const uint4* bh = reinterpret_cast<const uint4*>(g_Bh) + kbeg * 144;
        uint4* dh = reinterpret_cast<uint4*>(smem + BH_OFF);
        for (int i = tid; i < nu4; i += 256)
            dh[i] = __ldg(&bh[i]);
    }
    __syncthreads();

    uint32_t bl_lane = (unsigned)(lane & 7) * 144u + ((unsigned)(lane >> 3) & 1u) * 16u;
    // bias float2 for this lane's column pair, per n2 half
    float2 bb[2];
    bb[0] = __ldg(&bias2[(lane & 3)]);
    bb[1] = __ldg(&bias2[4 + (lane & 3)]);

    for (int tile = stream; tile < NT; tile += NSTREAM) {
        int base_n = tile * TILEM;

        // stage A tile (128 rows) as fp16 hi/lo
        for (int i = tid; i < 2048; i += 256) {
            int r = i >> 4, col = i & 15;
            int n = base_n + r;
            float4 f = (n < NPTS) ? __ldg(&feats4[(size_t)n * 16 + col])
                                  : make_float4(0.f, 0.f, 0.f, 0.f);
            __half h0 = __float2half_rn(f.x), h1 = __float2half_rn(f.y);
            __half h2 = __float2half_rn(f.z), h3 = __float2half_rn(f.w);
            __half l0 = __float2half_rn(f.x - __half2float(h0));
            __half l1 = __float2half_rn(f.y - __half2float(h1));
            __half l2 = __float2half_rn(f.z - __half2float(h2));
            __half l3 = __float2half_rn(f.w - __half2float(h3));
            uint2 hv, lv;
            hv.x = (unsigned)reinterpret_cast<unsigned short&>(h0) |
                   ((unsigned)reinterpret_cast<unsigned short&>(h1) << 16);
            hv.y = (unsigned)reinterpret_cast<unsigned short&>(h2) |
                   ((unsigned)reinterpret_cast<unsigned short&>(h3) << 16);
            lv.x = (unsigned)reinterpret_cast<unsigned short&>(l0) |
                   ((unsigned)reinterpret_cast<unsigned short&>(l1) << 16);
            lv.y = (unsigned)reinterpret_cast<unsigned short&>(l2) |
                   ((unsigned)reinterpret_cast<unsigned short&>(l3) << 16);
            unsigned off = (unsigned)r * 144u + (unsigned)col * 8u;
            *reinterpret_cast<uint2*>(smem + AH_OFF + off) = hv;
            *reinterpret_cast<uint2*>(smem + AL_OFF + off) = lv;
        }
        __syncthreads();

        // per-warp A fragments (16 rows)
        uint32_t ah[4][4], al[4][4];
        {
            uint32_t abase = sb + AH_OFF + (unsigned)(wid * 16 + (lane & 15)) * 144u
                           + ((unsigned)(lane >> 4) & 1u) * 16u;
#pragma unroll
            for (int kk = 0; kk < 4; kk++) {
                uint32_t a0 = abase + kk * 32u;
                asm volatile("ldmatrix.sync.aligned.m8n8.x4.shared.b16 {%0,%1,%2,%3},[%4];"
                    : "=r"(ah[kk][0]), "=r"(ah[kk][1]), "=r"(ah[kk][2]), "=r"(ah[kk][3]) : "r"(a0));
                uint32_t a1 = a0 + (AL_OFF - AH_OFF);
                asm volatile("ldmatrix.sync.aligned.m8n8.x4.shared.b16 {%0,%1,%2,%3},[%4];"
                    : "=r"(al[kk][0]), "=r"(al[kk][1]), "=r"(al[kk][2]), "=r"(al[kk][3]) : "r"(a1));
            }
        }
        __syncthreads();            // all frags read before next A restage

#pragma unroll 1
        for (int k = kbeg; k < kend; k++) {
            // coalesced rank load (lanes 0..15 hold rows) — guarded
            unsigned rank = 0xFFFFFFFFu;
            int rown = base_n + wid * 16 + lane;
            if (lane < 16 && rown < NPTS)
                rank = __ldg(&g_rank[(size_t)k * NPTS + rown]);

            // B fragments for this k, loaded once
            uint32_t bh[4][2][2];
            uint32_t bk = sb + BH_OFF + (unsigned)(k - kbeg) * 2304u + bl_lane;
#pragma unroll
            for (int kk = 0; kk < 4; kk++) {
#pragma unroll
                for (int n2 = 0; n2 < 2; n2++) {
                    uint32_t ba = bk + (unsigned)(n2 * 8) * 144u + (unsigned)kk * 32u;
                    asm volatile("ldmatrix.sync.aligned.m8n8.x2.shared.b16 {%0,%1},[%2];"
                                 : "=r"(bh[kk][n2][0]), "=r"(bh[kk][n2][1])
                                 : "r"(ba));
                }
            }

            float c[2][4];
#pragma unroll
            for (int n2 = 0; n2 < 2; n2++)
#pragma unroll
                for (int q = 0; q < 4; q++) c[n2][q] = 0.f;

#pragma unroll
            for (int kk = 0; kk < 4; kk++) {
#pragma unroll
                for (int n2 = 0; n2 < 2; n2++) {
                    MMA(c[n2], ah[kk], bh[kk][n2][0], bh[kk][n2][1]);
                    MMA(c[n2], al[kk], bh[kk][n2][0], bh[kk][n2][1]);
                }
            }

            // register-direct epilogue: lane owns rows (lane>>2) and (lane>>2)+8,
            // cols n2*8 + (lane&3)*2 + {0,1}
            unsigned rr0 = __shfl_sync(0xffffffffu, rank, lane >> 2);
            unsigned rr1 = __shfl_sync(0xffffffffu, rank, (lane >> 2) + 8);
            int colb = (lane & 3) * 2;
#pragma unroll
            for (int n2 = 0; n2 < 2; n2++) {
                if (rr0 != 0xFFFFFFFFu) {
                    float* dst = out + (size_t)(rr0 & 0x7FFFFFFFu) * 16 + n2 * 8 + colb;
                    if (rr0 & 0x80000000u) {
                        asm volatile("red.global.add.v2.f32 [%0], {%1,%2};"
                                     :: "l"(dst), "f"(c[n2][0]), "f"(c[n2][1]) : "memory");
                    } else {
                        *reinterpret_cast<float2*>(dst) =
                            make_float2(c[n2][0] + bb[n2].x, c[n2][1] + bb[n2].y);
                    }
                }
                if (rr1 != 0xFFFFFFFFu) {
                    float* dst = out + (size_t)(rr1 & 0x7FFFFFFFu) * 16 + n2 * 8 + colb;
                    if (rr1 & 0x80000000u) {
                        asm volatile("red.global.add.v2.f32 [%0], {%1,%2};"
                                     :: "l"(dst), "f"(c[n2][2]), "f"(c[n2][3]) : "memory");
                    } else {
                        *reinterpret_cast<float2*>(dst) =
                            make_float2(c[n2][2] + bb[n2].x, c[n2][3] + bb[n2].y);
                    }
                }
            }
        }
    }
}

// ---------------- launch ----------------
extern "C" void kernel_launch(void* const* d_in, const int* in_sizes, int n_in,
                              void* d_out, int out_size) {
    const float* feats = (const float*)d_in[0];
    const int*   coords = (const int*)d_in[1];
    const float* W = (const float*)d_in[2];
    const float* bias = (const float*)d_in[3];
    float* out = (float*)d_out;
    float* uniqf = out + (size_t)NKTOT * 16;

    cudaFuncSetAttribute(k_gemm, cudaFuncAttributeMaxDynamicSharedMemorySize, SMEM_SZ);

    k_zero<<<2 * ZBLK + 27, 256>>>(W);
    k_mark<<<(NPTS + 255) / 256, 256>>>((const int4*)coords);
    k_scan1<<<NPART, 256>>>();
    k_scan2<<<1, 512>>>();
    k_combo<<<NPART + FOB, 256>>>((float4*)out, (const float4*)bias, uniqf);
    k_rank<<<(NPTS + 255) / 256, 256>>>((const int4*)coords);
    k_gemm<<<2 * NSTREAM, 256, SMEM_SZ>>>((const float4*)feats, out, (const float2*)bias);
    k_emit<<<(WORDS + 255) / 256, 256>>>(uniqf);
}

// round 14
// speedup vs baseline: 1.0668x; 1.0668x over previous
#include <cuda_runtime.h>
#include <cuda_fp16.h>
#include <cstdint>

#define NPTS   200000
#define CIN    64
#define COUT   16
#define SXD    998
#define SYD    998
#define SZD    38
#define YZ     37924          /* SYD*SZD */
#define SENTV  37848152u
#define NKTOT  5400000        /* NPTS*27 */
#define WORDS  1182755
#define CHUNK  4096
#define NPART  289
#define WPAD   (NPART*CHUNK)
#define ZBLK   (WPAD/1024)
#define FOB    512

#define NOUT   432            /* 27*16 */
#define BSTR   72             /* padded row stride (fp16 elems) = 144B */
#define TILEM  128
#define NT     1563           /* ceil(200000/128) */
#define KB0    14             /* k split: [0,14) and [14,27) */
#define NSTREAM 222           /* tile streams; grid = 2*NSTREAM = 444 = 3/SM */

/* smem layout (bytes) */
#define AH_OFF   0            /* 128*144 = 18432 */
#define BH_OFF   18432        /* 224*144 = 32256 max */
#define SMEM_SZ  50688        /* 3 CTAs/SM comfortably */

// ---------------- device scratch ----------------
__device__ __align__(16) unsigned g_bitmap[WPAD];
__device__ __align__(16) unsigned g_coll[WPAD];
__device__ __align__(16) unsigned g_pref[WPAD];
__device__ __align__(16) unsigned g_rank[27 * NPTS];
__device__ __align__(16) unsigned short g_Bh[NOUT * BSTR];
__device__ unsigned g_part[NPART];
__device__ unsigned g_M;

static __device__ __forceinline__ uint32_t smem_u32(const void* p) {
    uint32_t a;
    asm("{ .reg .u64 t; cvta.to.shared.u64 t, %1; cvt.u32.u64 %0, t; }" : "=r"(a) : "l"(p));
    return a;
}

#define MMA(C, A, b0v, b1v) \
    asm volatile("mma.sync.aligned.m16n8k16.row.col.f32.f16.f16.f32 " \
        "{%0,%1,%2,%3},{%4,%5,%6,%7},{%8,%9},{%0,%1,%2,%3};" \
        : "+f"((C)[0]), "+f"((C)[1]), "+f"((C)[2]), "+f"((C)[3]) \
        : "r"((A)[0]), "r"((A)[1]), "r"((A)[2]), "r"((A)[3]), "r"(b0v), "r"(b1v))

// ---------------- kernels ----------------
// zero both bitmaps + build padded fp16 B [og][c]
__global__ void k_zero(const float* __restrict__ W) {
    if (blockIdx.x < 2 * ZBLK) {
        unsigned* dst = (blockIdx.x < ZBLK) ? g_bitmap : g_coll;
        unsigned b = (blockIdx.x < ZBLK) ? blockIdx.x : blockIdx.x - ZBLK;
        unsigned i = b * 1024 + threadIdx.x * 4;
        *reinterpret_cast<uint4*>(&dst[i]) = make_uint4(0u, 0u, 0u, 0u);
    } else {
        int k = blockIdx.x - 2 * ZBLK;
#pragma unroll
        for (int u = 0; u < 4; u++) {
            int idx = threadIdx.x + u * 256;
            int o = idx >> 6, c = idx & 63;
            float v = W[k * 1024 + c * 16 + o];
            __half h = __float2half_rn(v);
            int og = k * 16 + o;
            g_Bh[og * BSTR + c] = reinterpret_cast<unsigned short&>(h);
        }
    }
}

__global__ void k_mark(const int4* __restrict__ coords) {
    int n = blockIdx.x * blockDim.x + threadIdx.x;
    if (n >= NPTS) return;
    int4 c = coords[n];
#pragma unroll
    for (int k = 0; k < 27; k++) {
        int ox = c.y - k / 9;
        int oy = c.z - (k / 3) % 3;
        int oz = c.w - k % 3;
        if ((unsigned)ox < SXD && (unsigned)oy < SYD && (unsigned)oz < SZD) {
            unsigned lin = (unsigned)ox * YZ + (unsigned)oy * SZD + (unsigned)oz;
            unsigned bit = 1u << (lin & 31);
            unsigned old = atomicOr(&g_bitmap[lin >> 5], bit);
            if (old & bit) atomicOr(&g_coll[lin >> 5], bit);
        }
    }
}

__global__ void k_scan1() {
    __shared__ unsigned sh[256];
    unsigned base = blockIdx.x * CHUNK + threadIdx.x * 16;
    unsigned s = 0;
#pragma unroll
    for (int i = 0; i < 16; i += 4) {
        uint4 v = *reinterpret_cast<const uint4*>(&g_bitmap[base + i]);
        s += __popc(v.x) + __popc(v.y) + __popc(v.z) + __popc(v.w);
    }
    sh[threadIdx.x] = s;
    __syncthreads();
    for (int off = 128; off > 0; off >>= 1) {
        if (threadIdx.x < (unsigned)off) sh[threadIdx.x] += sh[threadIdx.x + off];
        __syncthreads();
    }
    if (threadIdx.x == 0) g_part[blockIdx.x] = sh[0];
}

__global__ void k_scan2() {
    __shared__ unsigned sh[512];
    unsigned t = threadIdx.x;
    unsigned v = (t < NPART) ? g_part[t] : 0u;
    sh[t] = v;
    __syncthreads();
    for (int off = 1; off < 512; off <<= 1) {
        unsigned add = (t >= (unsigned)off) ? sh[t - off] : 0u;
        __syncthreads();
        sh[t] += add;
        __syncthreads();
    }
    if (t < NPART) g_part[t] = sh[t] - v;
    if (t == NPART - 1) g_M = sh[t];
}

// combo: blocks [0,NPART): per-word prefix + bias-init of COLLISION rows only;
//        remaining blocks: zero tail rows (j>=M) + SENT-pad uniq tail
__global__ void k_combo(float4* __restrict__ out4, const float4* __restrict__ bias4,
                        float* __restrict__ uniqf) {
    if (blockIdx.x < NPART) {
        float4 bsv[4];
#pragma unroll
        for (int j = 0; j < 4; j++) bsv[j] = __ldg(&bias4[j]);
        __shared__ unsigned sh[256];
        unsigned base = blockIdx.x * CHUNK + threadIdx.x * 16;
        unsigned w[16];
#pragma unroll
        for (int i = 0; i < 16; i += 4)
            *reinterpret_cast<uint4*>(&w[i]) = *reinterpret_cast<const uint4*>(&g_bitmap[base + i]);
        unsigned s = 0;
#pragma unroll
        for (int i = 0; i < 16; i++) s += __popc(w[i]);
        sh[threadIdx.x] = s;
        __syncthreads();
        for (int off = 1; off < 256; off <<= 1) {
            unsigned add = (threadIdx.x >= (unsigned)off) ? sh[threadIdx.x - off] : 0u;
            __syncthreads();
            sh[threadIdx.x] += add;
            __syncthreads();
        }
        unsigned run = g_part[blockIdx.x] + (sh[threadIdx.x] - s);
#pragma unroll 1
        for (int i = 0; i < 16; i++) {
            g_pref[base + i] = run;
            unsigned bits = w[i];
            if (bits) {
                unsigned collw = g_coll[base + i] & bits;
                unsigned r0 = run;
                run += __popc(bits);
                while (collw) {
                    unsigned b = __ffs(collw) - 1u;
                    collw &= collw - 1u;
                    unsigned r = r0 + __popc(bits & ((1u << b) - 1u));
                    float4* o = out4 + (size_t)r * 4;
                    o[0] = bsv[0]; o[1] = bsv[1]; o[2] = bsv[2]; o[3] = bsv[3];
                }
            }
        }
    } else {
        unsigned gt = (blockIdx.x - NPART) * 256u + threadIdx.x;
        unsigned stride = (gridDim.x - NPART) * 256u;
        unsigned M = g_M;
        const float4 z4 = make_float4(0.f, 0.f, 0.f, 0.f);
        for (unsigned i = M * 4u + gt; i < (unsigned)NKTOT * 4u; i += stride)
            out4[i] = z4;
        for (unsigned j = M + gt; j < (unsigned)NKTOT; j += stride)
            uniqf[j] = 37848152.0f;
    }
}

// precompute rank[k][n] (0xFFFFFFFF = invalid; bit31 = collision)
__global__ void k_rank(const int4* __restrict__ coords) {
    int n = blockIdx.x * blockDim.x + threadIdx.x;
    if (n >= NPTS) return;
    int4 c = coords[n];
#pragma unroll
    for (int k = 0; k < 27; k++) {
        int ox = c.y - k / 9;
        int oy = c.z - (k / 3) % 3;
        int oz = c.w - k % 3;
        unsigned rank = 0xFFFFFFFFu;
        if ((unsigned)ox < SXD && (unsigned)oy < SYD && (unsigned)oz < SZD) {
            unsigned lin = (unsigned)ox * YZ + (unsigned)oy * SZD + (unsigned)oz;
            unsigned word = lin >> 5;
            unsigned bpos = lin & 31;
            rank = __ldg(&g_pref[word]) +
                   __popc(__ldg(&g_bitmap[word]) & ((1u << bpos) - 1u));
            if ((__ldg(&g_coll[word]) >> bpos) & 1u) rank |= 0x80000000u;
        }
        g_rank[k * NPTS + n] = rank;
    }
}

__global__ void k_emit(float* __restrict__ uniqf) {
    unsigned i = blockIdx.x * blockDim.x + threadIdx.x;
    if (i >= WORDS) return;
    unsigned bits = g_bitmap[i];
    if (!bits) return;
    unsigned r = g_pref[i];
    unsigned vbase = i << 5;
    while (bits) {
        unsigned b = __ffs(bits) - 1u;
        bits &= bits - 1u;
        uniqf[r++] = (float)(vbase + b);
    }
}

// ---- persistent fp16 HMMA GEMM (single-A-pass) + collision-split scatter ----
__global__ void __launch_bounds__(256, 3) k_gemm(
    const float4* __restrict__ feats4, float* __restrict__ out,
    const float4* __restrict__ bias4)
{
    extern __shared__ char smem[];
    uint32_t sb = smem_u32(smem);
    int tid = threadIdx.x;
    int wid = tid >> 5;
    int lane = tid & 31;
    int khalf = blockIdx.x & 1;
    int stream = blockIdx.x >> 1;
    int kbeg = khalf ? KB0 : 0;
    int kend = khalf ? 27 : KB0;

    // stage B (fp16) for our k-range ONCE
    {
        int nu4 = (kend - kbeg) * 144;
        const uint4* bh = reinterpret_cast<const uint4*>(g_Bh) + kbeg * 144;
        uint4* dh = reinterpret_cast<uint4*>(smem + BH_OFF);
        for (int i = tid; i < nu4; i += 256)
            dh[i] = __ldg(&bh[i]);
    }

    char* ebuf = smem + wid * 1024;             // 16 rows x 64B (aliases A region)
    uint32_t bl_lane = (unsigned)(lane & 7) * 144u + ((unsigned)(lane >> 3) & 1u) * 16u;
    float4 bq = __ldg(&bias4[lane & 3]);        // bias quarter for this lane's q

    for (int tile = stream; tile < NT; tile += NSTREAM) {
        int base_n = tile * TILEM;
        __syncthreads();                        // prev tile's ebuf done; B stage done

        // stage A tile (128 rows) as fp16
        for (int i = tid; i < 2048; i += 256) {
            int r = i >> 4, col = i & 15;
            int n = base_n + r;
            float4 f = (n < NPTS) ? __ldg(&feats4[(size_t)n * 16 + col])
                                  : make_float4(0.f, 0.f, 0.f, 0.f);
            __half h0 = __float2half_rn(f.x), h1 = __float2half_rn(f.y);
            __half h2 = __float2half_rn(f.z), h3 = __float2half_rn(f.w);
            uint2 hv;
            hv.x = (unsigned)reinterpret_cast<unsigned short&>(h0) |
                   ((unsigned)reinterpret_cast<unsigned short&>(h1) << 16);
            hv.y = (unsigned)reinterpret_cast<unsigned short&>(h2) |
                   ((unsigned)reinterpret_cast<unsigned short&>(h3) << 16);
            unsigned off = (unsigned)r * 144u + (unsigned)col * 8u;
            *reinterpret_cast<uint2*>(smem + AH_OFF + off) = hv;
        }
        __syncthreads();

        // per-warp A fragments (16 rows)
        uint32_t ah[4][4];
        {
            uint32_t abase = sb + AH_OFF + (unsigned)(wid * 16 + (lane & 15)) * 144u
                           + ((unsigned)(lane >> 4) & 1u) * 16u;
#pragma unroll
            for (int kk = 0; kk < 4; kk++) {
                uint32_t a0 = abase + kk * 32u;
                asm volatile("ldmatrix.sync.aligned.m8n8.x4.shared.b16 {%0,%1,%2,%3},[%4];"
                    : "=r"(ah[kk][0]), "=r"(ah[kk][1]), "=r"(ah[kk][2]), "=r"(ah[kk][3]) : "r"(a0));
            }
        }
        __syncthreads();                        // all frags read before ebuf writes

#pragma unroll 1
        for (int k = kbeg; k < kend; k++) {
            // coalesced rank load (lanes 0..15 hold rows) — guarded
            unsigned rank = 0xFFFFFFFFu;
            int rown = base_n + wid * 16 + lane;
            if (lane < 16 && rown < NPTS)
                rank = __ldg(&g_rank[(size_t)k * NPTS + rown]);

            // B fragments for this k, loaded once
            uint32_t bh[4][2][2];
            uint32_t bk = sb + BH_OFF + (unsigned)(k - kbeg) * 2304u + bl_lane;
#pragma unroll
            for (int kk = 0; kk < 4; kk++) {
#pragma unroll
                for (int n2 = 0; n2 < 2; n2++) {
                    uint32_t ba = bk + (unsigned)(n2 * 8) * 144u + (unsigned)kk * 32u;
                    asm volatile("ldmatrix.sync.aligned.m8n8.x2.shared.b16 {%0,%1},[%2];"
                                 : "=r"(bh[kk][n2][0]), "=r"(bh[kk][n2][1])
                                 : "r"(ba));
                }
            }

            float c[2][4];
#pragma unroll
            for (int n2 = 0; n2 < 2; n2++)
#pragma unroll
                for (int q = 0; q < 4; q++) c[n2][q] = 0.f;

#pragma unroll
            for (int kk = 0; kk < 4; kk++) {
#pragma unroll
                for (int n2 = 0; n2 < 2; n2++) {
                    MMA(c[n2], ah[kk], bh[kk][n2][0], bh[kk][n2][1]);
                }
            }

            __syncwarp();
            {
                int r0 = lane >> 2;
                int cb = (lane & 3) * 2;
#pragma unroll
                for (int n2 = 0; n2 < 2; n2++) {
                    int colb = n2 * 8 + cb;
                    *reinterpret_cast<float2*>(ebuf + r0 * 64 + colb * 4) =
                        make_float2(c[n2][0], c[n2][1]);
                    *reinterpret_cast<float2*>(ebuf + (r0 + 8) * 64 + colb * 4) =
                        make_float2(c[n2][2], c[n2][3]);
                }
            }
            __syncwarp();
#pragma unroll
            for (int j = 0; j < 2; j++) {
                int rw = j * 8 + (lane >> 2);
                int q = lane & 3;
                unsigned rr = __shfl_sync(0xffffffffu, rank, rw);
                if (rr != 0xFFFFFFFFu) {
                    float4 v = *reinterpret_cast<const float4*>(ebuf + rw * 64 + q * 16);
                    if (rr & 0x80000000u) {
                        asm volatile("red.global.add.v4.f32 [%0], {%1,%2,%3,%4};"
                                     :: "l"(out + (size_t)(rr & 0x7FFFFFFFu) * 16 + q * 4),
                                        "f"(v.x), "f"(v.y), "f"(v.z), "f"(v.w)
                                     : "memory");
                    } else {
                        float4 w = make_float4(v.x + bq.x, v.y + bq.y,
                                               v.z + bq.z, v.w + bq.w);
                        *reinterpret_cast<float4*>(out + (size_t)rr * 16 + q * 4) = w;
                    }
                }
            }
            __syncwarp();
        }
    }
}

// ---------------- launch ----------------
extern "C" void kernel_launch(void* const* d_in, const int* in_sizes, int n_in,
                              void* d_out, int out_size) {
    const float* feats = (const float*)d_in[0];
    const int*   coords = (const int*)d_in[1];
    const float* W = (const float*)d_in[2];
    const float* bias = (const float*)d_in[3];
    float* out = (float*)d_out;
    float* uniqf = out + (size_t)NKTOT * 16;

    cudaFuncSetAttribute(k_gemm, cudaFuncAttributeMaxDynamicSharedMemorySize, SMEM_SZ);

    k_zero<<<2 * ZBLK + 27, 256>>>(W);
    k_mark<<<(NPTS + 255) / 256, 256>>>((const int4*)coords);
    k_scan1<<<NPART, 256>>>();
    k_scan2<<<1, 512>>>();
    k_combo<<<NPART + FOB, 256>>>((float4*)out, (const float4*)bias, uniqf);
    k_rank<<<(NPTS + 255) / 256, 256>>>((const int4*)coords);
    k_gemm<<<2 * NSTREAM, 256, SMEM_SZ>>>((const float4*)feats, out, (const float4*)bias);
    k_emit<<<(WORDS + 255) / 256, 256>>>(uniqf);
}

// round 15
// speedup vs baseline: 1.3010x; 1.2196x over previous
#include <cuda_runtime.h>
#include <cuda_fp16.h>
#include <cstdint>

#define NPTS   200000
#define CIN    64
#define COUT   16
#define SXD    998
#define SYD    998
#define SZD    38
#define YZ     37924          /* SYD*SZD */
#define SENTV  37848152u
#define NKTOT  5400000        /* NPTS*27 */
#define WORDS  1182755
#define CHUNK  4096
#define NPART  289
#define WPAD   (NPART*CHUNK)
#define ZBLK   (WPAD/1024)
#define FOB    512

#define NOUT   432            /* 27*16 */
#define BSTR   72             /* padded row stride (fp16 elems) = 144B */
#define TILEM  128
#define NT     1563           /* ceil(200000/128) */
#define KB0    14             /* k split: [0,14) and [14,27) */
#define NSTREAM 222           /* tile streams; grid = 2*NSTREAM = 444 = 3/SM */

/* smem layout (bytes) */
#define AH_OFF   0            /* 128*144 = 18432 */
#define BH_OFF   18432        /* 224*144 = 32256 max */
#define SMEM_SZ  50688        /* 3 CTAs/SM comfortably */

// ---------------- device scratch ----------------
__device__ __align__(16) unsigned g_bitmap[WPAD];
__device__ __align__(16) unsigned g_coll[WPAD];
__device__ __align__(16) unsigned g_pref[WPAD];
__device__ __align__(16) unsigned g_rank[27 * NPTS];
__device__ __align__(16) unsigned short g_Bh[NOUT * BSTR];
__device__ unsigned g_part[NPART];
__device__ unsigned g_M;

static __device__ __forceinline__ uint32_t smem_u32(const void* p) {
    uint32_t a;
    asm("{ .reg .u64 t; cvta.to.shared.u64 t, %1; cvt.u32.u64 %0, t; }" : "=r"(a) : "l"(p));
    return a;
}

#define MMA(C, A, b0v, b1v) \
    asm volatile("mma.sync.aligned.m16n8k16.row.col.f32.f16.f16.f32 " \
        "{%0,%1,%2,%3},{%4,%5,%6,%7},{%8,%9},{%0,%1,%2,%3};" \
        : "+f"((C)[0]), "+f"((C)[1]), "+f"((C)[2]), "+f"((C)[3]) \
        : "r"((A)[0]), "r"((A)[1]), "r"((A)[2]), "r"((A)[3]), "r"(b0v), "r"(b1v))

// ---------------- kernels ----------------
// zero both bitmaps + build padded fp16 B [og][c]
__global__ void k_zero(const float* __restrict__ W) {
    if (blockIdx.x < 2 * ZBLK) {
        unsigned* dst = (blockIdx.x < ZBLK) ? g_bitmap : g_coll;
        unsigned b = (blockIdx.x < ZBLK) ? blockIdx.x : blockIdx.x - ZBLK;
        unsigned i = b * 1024 + threadIdx.x * 4;
        *reinterpret_cast<uint4*>(&dst[i]) = make_uint4(0u, 0u, 0u, 0u);
    } else {
        int k = blockIdx.x - 2 * ZBLK;
#pragma unroll
        for (int u = 0; u < 4; u++) {
            int idx = threadIdx.x + u * 256;
            int o = idx >> 6, c = idx & 63;
            float v = W[k * 1024 + c * 16 + o];
            __half h = __float2half_rn(v);
            int og = k * 16 + o;
            g_Bh[og * BSTR + c] = reinterpret_cast<unsigned short&>(h);
        }
    }
}

// mark with z-grouped word atomics: one atomicOr per (kx,ky) word
__global__ void k_mark(const int4* __restrict__ coords) {
    int n = blockIdx.x * blockDim.x + threadIdx.x;
    if (n >= NPTS) return;
    int4 c = coords[n];
    int z = c.w;
#pragma unroll
    for (int kxy = 0; kxy < 9; kxy++) {
        int ox = c.y - kxy / 3;
        int oy = c.z - kxy % 3;
        if ((unsigned)ox >= SXD || (unsigned)oy >= SYD) continue;
        unsigned lin0 = (unsigned)ox * YZ + (unsigned)oy * SZD + (unsigned)z;
        unsigned w0 = lin0 >> 5;
        unsigned m0 = 0, m1 = 0;
        unsigned w1 = 0;
#pragma unroll
        for (int kz = 0; kz < 3; kz++) {
            if ((unsigned)(z - kz) < SZD) {
                unsigned lin = lin0 - kz;
                unsigned w = lin >> 5;
                unsigned bit = 1u << (lin & 31);
                if (w == w0) m0 |= bit;
                else { w1 = w; m1 |= bit; }
            }
        }
        if (m0) {
            unsigned old = atomicOr(&g_bitmap[w0], m0);
            unsigned cb = old & m0;
            if (cb) atomicOr(&g_coll[w0], cb);
        }
        if (m1) {
            unsigned old = atomicOr(&g_bitmap[w1], m1);
            unsigned cb = old & m1;
            if (cb) atomicOr(&g_coll[w1], cb);
        }
    }
}

__global__ void k_scan1() {
    __shared__ unsigned sh[256];
    unsigned base = blockIdx.x * CHUNK + threadIdx.x * 16;
    unsigned s = 0;
#pragma unroll
    for (int i = 0; i < 16; i += 4) {
        uint4 v = *reinterpret_cast<const uint4*>(&g_bitmap[base + i]);
        s += __popc(v.x) + __popc(v.y) + __popc(v.z) + __popc(v.w);
    }
    sh[threadIdx.x] = s;
    __syncthreads();
    for (int off = 128; off > 0; off >>= 1) {
        if (threadIdx.x < (unsigned)off) sh[threadIdx.x] += sh[threadIdx.x + off];
        __syncthreads();
    }
    if (threadIdx.x == 0) g_part[blockIdx.x] = sh[0];
}

__global__ void k_scan2() {
    __shared__ unsigned sh[512];
    unsigned t = threadIdx.x;
    unsigned v = (t < NPART) ? g_part[t] : 0u;
    sh[t] = v;
    __syncthreads();
    for (int off = 1; off < 512; off <<= 1) {
        unsigned add = (t >= (unsigned)off) ? sh[t - off] : 0u;
        __syncthreads();
        sh[t] += add;
        __syncthreads();
    }
    if (t < NPART) g_part[t] = sh[t] - v;
    if (t == NPART - 1) g_M = sh[t];
}

// combo: blocks [0,NPART): per-word prefix + bias-init of COLLISION rows only;
//        remaining blocks: zero tail rows (j>=M) + SENT-pad uniq tail
__global__ void k_combo(float4* __restrict__ out4, const float4* __restrict__ bias4,
                        float* __restrict__ uniqf) {
    if (blockIdx.x < NPART) {
        float4 bsv[4];
#pragma unroll
        for (int j = 0; j < 4; j++) bsv[j] = __ldg(&bias4[j]);
        __shared__ unsigned sh[256];
        unsigned base = blockIdx.x * CHUNK + threadIdx.x * 16;
        unsigned w[16];
#pragma unroll
        for (int i = 0; i < 16; i += 4)
            *reinterpret_cast<uint4*>(&w[i]) = *reinterpret_cast<const uint4*>(&g_bitmap[base + i]);
        unsigned s = 0;
#pragma unroll
        for (int i = 0; i < 16; i++) s += __popc(w[i]);
        sh[threadIdx.x] = s;
        __syncthreads();
        for (int off = 1; off < 256; off <<= 1) {
            unsigned add = (threadIdx.x >= (unsigned)off) ? sh[threadIdx.x - off] : 0u;
            __syncthreads();
            sh[threadIdx.x] += add;
            __syncthreads();
        }
        unsigned run = g_part[blockIdx.x] + (sh[threadIdx.x] - s);
#pragma unroll 1
        for (int i = 0; i < 16; i++) {
            g_pref[base + i] = run;
            unsigned bits = w[i];
            if (bits) {
                unsigned collw = g_coll[base + i] & bits;
                unsigned r0 = run;
                run += __popc(bits);
                while (collw) {
                    unsigned b = __ffs(collw) - 1u;
                    collw &= collw - 1u;
                    unsigned r = r0 + __popc(bits & ((1u << b) - 1u));
                    float4* o = out4 + (size_t)r * 4;
                    o[0] = bsv[0]; o[1] = bsv[1]; o[2] = bsv[2]; o[3] = bsv[3];
                }
            }
        }
    } else {
        unsigned gt = (blockIdx.x - NPART) * 256u + threadIdx.x;
        unsigned stride = (gridDim.x - NPART) * 256u;
        unsigned M = g_M;
        const float4 z4 = make_float4(0.f, 0.f, 0.f, 0.f);
        for (unsigned i = M * 4u + gt; i < (unsigned)NKTOT * 4u; i += stride)
            out4[i] = z4;
        for (unsigned j = M + gt; j < (unsigned)NKTOT; j += stride)
            uniqf[j] = 37848152.0f;
    }
}

// precompute rank[k][n] with z-grouped word loads (one {pref,bm,coll} triple
// per (kx,ky) group, boundary fallback). 0xFFFFFFFF = invalid; bit31 = collision.
__global__ void k_rank(const int4* __restrict__ coords) {
    int n = blockIdx.x * blockDim.x + threadIdx.x;
    if (n >= NPTS) return;
    int4 c = coords[n];
    int z = c.w;
#pragma unroll
    for (int kxy = 0; kxy < 9; kxy++) {
        int ox = c.y - kxy / 3;
        int oy = c.z - kxy % 3;
        int kbase = kxy * 3;
        bool xyv = (unsigned)ox < SXD && (unsigned)oy < SYD;
        unsigned lin0 = 0, w0 = 0, pref0 = 0, bm0 = 0, cl0 = 0;
        if (xyv) {
            lin0 = (unsigned)ox * YZ + (unsigned)oy * SZD + (unsigned)z;
            w0 = lin0 >> 5;
            pref0 = __ldg(&g_pref[w0]);
            bm0 = __ldg(&g_bitmap[w0]);
            cl0 = __ldg(&g_coll[w0]);
        }
#pragma unroll
        for (int kz = 0; kz < 3; kz++) {
            unsigned rank = 0xFFFFFFFFu;
            if (xyv && (unsigned)(z - kz) < SZD) {
                unsigned lin = lin0 - kz;
                unsigned w = lin >> 5;
                unsigned bpos = lin & 31;
                unsigned pref, bm, cl;
                if (w == w0) { pref = pref0; bm = bm0; cl = cl0; }
                else {
                    pref = __ldg(&g_pref[w]);
                    bm = __ldg(&g_bitmap[w]);
                    cl = __ldg(&g_coll[w]);
                }
                rank = pref + __popc(bm & ((1u << bpos) - 1u));
                if ((cl >> bpos) & 1u) rank |= 0x80000000u;
            }
            g_rank[(kbase + kz) * NPTS + n] = rank;
        }
    }
}

__global__ void k_emit(float* __restrict__ uniqf) {
    unsigned i = blockIdx.x * blockDim.x + threadIdx.x;
    if (i >= WORDS) return;
    unsigned bits = g_bitmap[i];
    if (!bits) return;
    unsigned r = g_pref[i];
    unsigned vbase = i << 5;
    while (bits) {
        unsigned b = __ffs(bits) - 1u;
        bits &= bits - 1u;
        uniqf[r++] = (float)(vbase + b);
    }
}

// ---- persistent fp16 HMMA GEMM (single-A-pass) + collision-split scatter ----
__global__ void __launch_bounds__(256, 3) k_gemm(
    const float4* __restrict__ feats4, float* __restrict__ out,
    const float4* __restrict__ bias4)
{
    extern __shared__ char smem[];
    uint32_t sb = smem_u32(smem);
    int tid = threadIdx.x;
    int wid = tid >> 5;
    int lane = tid & 31;
    int khalf = blockIdx.x & 1;
    int stream = blockIdx.x >> 1;
    int kbeg = khalf ? KB0 : 0;
    int kend = khalf ? 27 : KB0;

    // stage B (fp16) for our k-range ONCE
    {
        int nu4 = (kend - kbeg) * 144;
        const uint4* bh = reinterpret_cast<const uint4*>(g_Bh) + kbeg * 144;
        uint4* dh = reinterpret_cast<uint4*>(smem + BH_OFF);
        for (int i = tid; i < nu4; i += 256)
            dh[i] = __ldg(&bh[i]);
    }

    char* ebuf = smem + wid * 1024;             // 16 rows x 64B (aliases A region)
    uint32_t bl_lane = (unsigned)(lane & 7) * 144u + ((unsigned)(lane >> 3) & 1u) * 16u;
    float4 bq = __ldg(&bias4[lane & 3]);        // bias quarter for this lane's q

    for (int tile = stream; tile < NT; tile += NSTREAM) {
        int base_n = tile * TILEM;
        __syncthreads();                        // prev tile's ebuf done; B stage done

        // stage A tile (128 rows) as fp16
        for (int i = tid; i < 2048; i += 256) {
            int r = i >> 4, col = i & 15;
            int n = base_n + r;
            float4 f = (n < NPTS) ? __ldg(&feats4[(size_t)n * 16 + col])
                                  : make_float4(0.f, 0.f, 0.f, 0.f);
            __half h0 = __float2half_rn(f.x), h1 = __float2half_rn(f.y);
            __half h2 = __float2half_rn(f.z), h3 = __float2half_rn(f.w);
            uint2 hv;
            hv.x = (unsigned)reinterpret_cast<unsigned short&>(h0) |
                   ((unsigned)reinterpret_cast<unsigned short&>(h1) << 16);
            hv.y = (unsigned)reinterpret_cast<unsigned short&>(h2) |
                   ((unsigned)reinterpret_cast<unsigned short&>(h3) << 16);
            unsigned off = (unsigned)r * 144u + (unsigned)col * 8u;
            *reinterpret_cast<uint2*>(smem + AH_OFF + off) = hv;
        }
        __syncthreads();

        // per-warp A fragments (16 rows)
        uint32_t ah[4][4];
        {
            uint32_t abase = sb + AH_OFF + (unsigned)(wid * 16 + (lane & 15)) * 144u
                           + ((unsigned)(lane >> 4) & 1u) * 16u;
#pragma unroll
            for (int kk = 0; kk < 4; kk++) {
                uint32_t a0 = abase + kk * 32u;
                asm volatile("ldmatrix.sync.aligned.m8n8.x4.shared.b16 {%0,%1,%2,%3},[%4];"
                    : "=r"(ah[kk][0]), "=r"(ah[kk][1]), "=r"(ah[kk][2]), "=r"(ah[kk][3]) : "r"(a0));
            }
        }
        __syncthreads();                        // all frags read before ebuf writes

#pragma unroll 1
        for (int k = kbeg; k < kend; k++) {
            // coalesced rank load (lanes 0..15 hold rows) — guarded
            unsigned rank = 0xFFFFFFFFu;
            int rown = base_n + wid * 16 + lane;
            if (lane < 16 && rown < NPTS)
                rank = __ldg(&g_rank[(size_t)k * NPTS + rown]);

            // B fragments for this k, loaded once
            uint32_t bh[4][2][2];
            uint32_t bk = sb + BH_OFF + (unsigned)(k - kbeg) * 2304u + bl_lane;
#pragma unroll
            for (int kk = 0; kk < 4; kk++) {
#pragma unroll
                for (int n2 = 0; n2 < 2; n2++) {
                    uint32_t ba = bk + (unsigned)(n2 * 8) * 144u + (unsigned)kk * 32u;
                    asm volatile("ldmatrix.sync.aligned.m8n8.x2.shared.b16 {%0,%1},[%2];"
                                 : "=r"(bh[kk][n2][0]), "=r"(bh[kk][n2][1])
                                 : "r"(ba));
                }
            }

            float c[2][4];
#pragma unroll
            for (int n2 = 0; n2 < 2; n2++)
#pragma unroll
                for (int q = 0; q < 4; q++) c[n2][q] = 0.f;

#pragma unroll
            for (int kk = 0; kk < 4; kk++) {
#pragma unroll
                for (int n2 = 0; n2 < 2; n2++) {
                    MMA(c[n2], ah[kk], bh[kk][n2][0], bh[kk][n2][1]);
                }
            }

            __syncwarp();
            {
                int r0 = lane >> 2;
                int cb = (lane & 3) * 2;
#pragma unroll
                for (int n2 = 0; n2 < 2; n2++) {
                    int colb = n2 * 8 + cb;
                    *reinterpret_cast<float2*>(ebuf + r0 * 64 + colb * 4) =
                        make_float2(c[n2][0], c[n2][1]);
                    *reinterpret_cast<float2*>(ebuf + (r0 + 8) * 64 + colb * 4) =
                        make_float2(c[n2][2], c[n2][3]);
                }
            }
            __syncwarp();
#pragma unroll
            for (int j = 0; j < 2; j++) {
                int rw = j * 8 + (lane >> 2);
                int q = lane & 3;
                unsigned rr = __shfl_sync(0xffffffffu, rank, rw);
                if (rr != 0xFFFFFFFFu) {
                    float4 v = *reinterpret_cast<const float4*>(ebuf + rw * 64 + q * 16);
                    if (rr & 0x80000000u) {
                        asm volatile("red.global.add.v4.f32 [%0], {%1,%2,%3,%4};"
                                     :: "l"(out + (size_t)(rr & 0x7FFFFFFFu) * 16 + q * 4),
                                        "f"(v.x), "f"(v.y), "f"(v.z), "f"(v.w)
                                     : "memory");
                    } else {
                        float4 w = make_float4(v.x + bq.x, v.y + bq.y,
                                               v.z + bq.z, v.w + bq.w);
                        *reinterpret_cast<float4*>(out + (size_t)rr * 16 + q * 4) = w;
                    }
                }
            }
            __syncwarp();
        }
    }
}

// ---------------- launch ----------------
extern "C" void kernel_launch(void* const* d_in, const int* in_sizes, int n_in,
                              void* d_out, int out_size) {
    const float* feats = (const float*)d_in[0];
    const int*   coords = (const int*)d_in[1];
    const float* W = (const float*)d_in[2];
    const float* bias = (const float*)d_in[3];
    float* out = (float*)d_out;
    float* uniqf = out + (size_t)NKTOT * 16;

    cudaFuncSetAttribute(k_gemm, cudaFuncAttributeMaxDynamicSharedMemorySize, SMEM_SZ);

    k_zero<<<2 * ZBLK + 27, 256>>>(W);
    k_mark<<<(NPTS + 255) / 256, 256>>>((const int4*)coords);
    k_scan1<<<NPART, 256>>>();
    k_scan2<<<1, 512>>>();
    k_combo<<<NPART + FOB, 256>>>((float4*)out, (const float4*)bias, uniqf);
    k_rank<<<(NPTS + 255) / 256, 256>>>((const int4*)coords);
    k_gemm<<<2 * NSTREAM, 256, SMEM_SZ>>>((const float4*)feats, out, (const float4*)bias);
    k_emit<<<(WORDS + 255) / 256, 256>>>(uniqf);
}